// round 1
// baseline (speedup 1.0000x reference)
#include <cuda_runtime.h>

#define B_ROWS 16384
#define D_DIM  1024
#define C_LAB  14
#define THREADS 256
#define ROWS_PER_BLOCK 16
#define NBLOCKS (B_ROWS / ROWS_PER_BLOCK)   // 1024

// Scratch (no allocations allowed in kernel_launch)
__device__ float g_margin[B_ROWS];
__device__ float g_partials[NBLOCKS];

// ---------------------------------------------------------------------------
// Kernel 1: per-row margins from labels (binary int32 labels, imposter = i+1 mod B)
// ---------------------------------------------------------------------------
__global__ void margin_kernel(const int* __restrict__ labels) {
    int i = blockIdx.x * blockDim.x + threadIdx.x;
    if (i >= B_ROWS) return;
    int j = (i + 1) & (B_ROWS - 1);
    const int* li = labels + (long)i * C_LAB;
    const int* lj = labels + (long)j * C_LAB;
    int n = 0, d = 0;
    bool eq = true;
    #pragma unroll
    for (int c = 0; c < C_LAB; c++) {
        int a = li[c], b = lj[c];
        eq = eq && (a == b);
        n += (a | b);
        d += (a ^ b);
    }
    float m;
    if (eq) {
        m = 0.0f;
    } else if (n > 0) {
        m = fmaxf(0.5f, (float)d / fmaxf((float)n, 1.0f));
    } else {
        m = 0.5f;
    }
    g_margin[i] = m;
}

// ---------------------------------------------------------------------------
// Kernel 2: streaming triple-dot + hinge. Each block owns ROWS_PER_BLOCK
// contiguous rows; "current" row slice lives in registers and is carried
// forward so each embedding row is loaded from HBM (at most) once per block.
// ---------------------------------------------------------------------------
__global__ __launch_bounds__(THREADS)
void rank_kernel(const float4* __restrict__ zi, const float4* __restrict__ zt) {
    __shared__ float red[THREADS / 32][3];

    const int t    = threadIdx.x;
    const int lane = t & 31;
    const int warp = t >> 5;
    const int RW   = D_DIM / 4;                  // 256 float4 per row
    const int r0   = blockIdx.x * ROWS_PER_BLOCK;

    // prime the carry with the first row of this chunk
    float4 ci = zi[(long)r0 * RW + t];
    float4 ct = zt[(long)r0 * RW + t];

    float acc = 0.0f;

    #pragma unroll 1
    for (int k = 0; k < ROWS_PER_BLOCK; k++) {
        const int r  = r0 + k;
        const int nr = (r + 1) & (B_ROWS - 1);

        float4 ni = zi[(long)nr * RW + t];
        float4 nt = zt[(long)nr * RW + t];

        float p = ci.x * ct.x + ci.y * ct.y + ci.z * ct.z + ci.w * ct.w;  // paired
        float a = ni.x * ct.x + ni.y * ct.y + ni.z * ct.z + ni.w * ct.w;  // imp_img
        float b = nt.x * ci.x + nt.y * ci.y + nt.z * ci.z + nt.w * ci.w;  // imp_txt

        #pragma unroll
        for (int o = 16; o > 0; o >>= 1) {
            p += __shfl_down_sync(0xffffffffu, p, o);
            a += __shfl_down_sync(0xffffffffu, a, o);
            b += __shfl_down_sync(0xffffffffu, b, o);
        }
        if (lane == 0) {
            red[warp][0] = p;
            red[warp][1] = a;
            red[warp][2] = b;
        }
        __syncthreads();
        if (t == 0) {
            float P = 0.0f, A = 0.0f, Bv = 0.0f;
            #pragma unroll
            for (int w = 0; w < THREADS / 32; w++) {
                P  += red[w][0];
                A  += red[w][1];
                Bv += red[w][2];
            }
            const float m = g_margin[r];
            acc += fmaxf(A - P + m, 0.0f) + fmaxf(Bv - P + m, 0.0f);
        }
        __syncthreads();   // protect red[] before next iteration overwrites

        ci = ni;           // carry: next becomes current
        ct = nt;
    }

    if (t == 0) g_partials[blockIdx.x] = acc;
}

// ---------------------------------------------------------------------------
// Kernel 3: deterministic reduction of the 1024 block partials -> scalar loss
// ---------------------------------------------------------------------------
__global__ void final_kernel(float* __restrict__ out) {
    __shared__ float s[32];
    const int t    = threadIdx.x;       // 1024 threads
    const int lane = t & 31;
    const int warp = t >> 5;

    float v = g_partials[t];
    #pragma unroll
    for (int o = 16; o > 0; o >>= 1) v += __shfl_down_sync(0xffffffffu, v, o);
    if (lane == 0) s[warp] = v;
    __syncthreads();
    if (warp == 0) {
        float x = s[lane];
        #pragma unroll
        for (int o = 16; o > 0; o >>= 1) x += __shfl_down_sync(0xffffffffu, x, o);
        if (t == 0) out[0] = x * (1.0f / (float)B_ROWS);
    }
}

// ---------------------------------------------------------------------------
extern "C" void kernel_launch(void* const* d_in, const int* in_sizes, int n_in,
                              void* d_out, int out_size) {
    const float* zi     = (const float*)d_in[0];   // z_image [16384,1024] f32
    const float* zt     = (const float*)d_in[1];   // z_text  [16384,1024] f32
    const int*   labels = (const int*)d_in[2];     // labels  [16384,14]   i32

    margin_kernel<<<(B_ROWS + 255) / 256, 256>>>(labels);
    rank_kernel<<<NBLOCKS, THREADS>>>((const float4*)zi, (const float4*)zt);
    final_kernel<<<1, 1024>>>((float*)d_out);
}

// round 2
// speedup vs baseline: 1.0096x; 1.0096x over previous
#include <cuda_runtime.h>

#define B_ROWS 16384
#define D_DIM  1024
#define C_LAB  14
#define THREADS 256
#define NWARPS  (THREADS / 32)              // 8
#define ROWS_PER_BLOCK 16
#define NBLOCKS (B_ROWS / ROWS_PER_BLOCK)   // 1024

__device__ float        g_partials[NBLOCKS];
__device__ unsigned int g_count = 0;        // self-resetting; safe across graph replays

// ---------------------------------------------------------------------------
// Single fused kernel: streaming triple-dot + inline margins + hinge +
// last-block-done global reduction. Hot loop has ZERO barriers so successive
// iterations' LDG.128s pipeline (MLP ~8 with unroll 4).
// ---------------------------------------------------------------------------
__global__ __launch_bounds__(THREADS)
void rank_fused_kernel(const float4* __restrict__ zi,
                       const float4* __restrict__ zt,
                       const int*    __restrict__ labels,
                       float*        __restrict__ out) {
    __shared__ float red[ROWS_PER_BLOCK][NWARPS][3];
    __shared__ float wsum[NWARPS];
    __shared__ int   is_last;

    const int t    = threadIdx.x;
    const int lane = t & 31;
    const int warp = t >> 5;
    const int RW   = D_DIM / 4;                  // 256 float4 per row
    const int r0   = blockIdx.x * ROWS_PER_BLOCK;

    // prime the carry with the first row of this chunk
    float4 ci = zi[(long)r0 * RW + t];
    float4 ct = zt[(long)r0 * RW + t];

    // ---- streaming phase: no barriers ----
    #pragma unroll 4
    for (int k = 0; k < ROWS_PER_BLOCK; k++) {
        const int nr = (r0 + k + 1) & (B_ROWS - 1);

        float4 ni = zi[(long)nr * RW + t];
        float4 nt = zt[(long)nr * RW + t];

        float p = ci.x * ct.x + ci.y * ct.y + ci.z * ct.z + ci.w * ct.w;  // paired
        float a = ni.x * ct.x + ni.y * ct.y + ni.z * ct.z + ni.w * ct.w;  // imp_img
        float b = nt.x * ci.x + nt.y * ci.y + nt.z * ci.z + nt.w * ci.w;  // imp_txt

        #pragma unroll
        for (int o = 16; o > 0; o >>= 1) {
            p += __shfl_down_sync(0xffffffffu, p, o);
            a += __shfl_down_sync(0xffffffffu, a, o);
            b += __shfl_down_sync(0xffffffffu, b, o);
        }
        if (lane == 0) {
            red[k][warp][0] = p;
            red[k][warp][1] = a;
            red[k][warp][2] = b;
        }
        ci = ni;           // carry: next becomes current
        ct = nt;
    }

    __syncthreads();       // the ONLY intra-loop-region barrier

    // ---- epilogue: threads 0..15 each finalize one row (margin + hinge) ----
    float acc = 0.0f;
    if (t < ROWS_PER_BLOCK) {
        const int r = r0 + t;
        const int j = (r + 1) & (B_ROWS - 1);

        // inline margin from labels (binary i32)
        const int* li = labels + (long)r * C_LAB;
        const int* lj = labels + (long)j * C_LAB;
        int n = 0, d = 0;
        bool eq = true;
        #pragma unroll
        for (int c = 0; c < C_LAB; c++) {
            int a = li[c], b = lj[c];
            eq = eq && (a == b);
            n += (a | b);
            d += (a ^ b);
        }
        float m;
        if (eq)        m = 0.0f;
        else if (n>0)  m = fmaxf(0.5f, (float)d / fmaxf((float)n, 1.0f));
        else           m = 0.5f;

        float P = 0.0f, A = 0.0f, Bv = 0.0f;
        #pragma unroll
        for (int w = 0; w < NWARPS; w++) {
            P  += red[t][w][0];
            A  += red[t][w][1];
            Bv += red[t][w][2];
        }
        acc = fmaxf(A - P + m, 0.0f) + fmaxf(Bv - P + m, 0.0f);
    }

    // reduce the 16 row-accs (all live in warp 0, lanes 0..15)
    if (warp == 0) {
        #pragma unroll
        for (int o = 8; o > 0; o >>= 1)
            acc += __shfl_down_sync(0xffffffffu, acc, o);
        if (lane == 0) {
            g_partials[blockIdx.x] = acc;
            __threadfence();
            unsigned old = atomicAdd(&g_count, 1u);
            is_last = (old == NBLOCKS - 1) ? 1 : 0;
        }
    }
    __syncthreads();

    // ---- last block reduces all partials (fixed order -> deterministic) ----
    if (is_last) {
        float v = 0.0f;
        #pragma unroll
        for (int i = t; i < NBLOCKS; i += THREADS)
            v += ((volatile float*)g_partials)[i];
        #pragma unroll
        for (int o = 16; o > 0; o >>= 1)
            v += __shfl_down_sync(0xffffffffu, v, o);
        if (lane == 0) wsum[warp] = v;
        __syncthreads();
        if (warp == 0) {
            float x = (lane < NWARPS) ? wsum[lane] : 0.0f;
            #pragma unroll
            for (int o = 4; o > 0; o >>= 1)
                x += __shfl_down_sync(0xffffffffu, x, o);
            if (t == 0) {
                out[0]  = x * (1.0f / (float)B_ROWS);
                g_count = 0;                 // reset for next graph replay
            }
        }
    }
}

// ---------------------------------------------------------------------------
extern "C" void kernel_launch(void* const* d_in, const int* in_sizes, int n_in,
                              void* d_out, int out_size) {
    const float* zi     = (const float*)d_in[0];   // z_image [16384,1024] f32
    const float* zt     = (const float*)d_in[1];   // z_text  [16384,1024] f32
    const int*   labels = (const int*)d_in[2];     // labels  [16384,14]   i32

    rank_fused_kernel<<<NBLOCKS, THREADS>>>((const float4*)zi, (const float4*)zt,
                                            labels, (float*)d_out);
}

// round 3
// speedup vs baseline: 1.1504x; 1.1394x over previous
#include <cuda_runtime.h>

#define B_ROWS 16384
#define D_DIM  1024
#define C_LAB  14
#define THREADS 256
#define NWARPS  (THREADS / 32)              // 8
#define GRID    740                          // 148 SMs x 5 blocks/SM -> single wave
#define MAX_ROWS 23                          // ceil(16384/740)

__device__ float        g_partials[GRID];
__device__ unsigned int g_count = 0;        // self-resetting; safe across graph replays

// ---------------------------------------------------------------------------
// Persistent-wave fused kernel: exactly one wave of 740 CTAs, each owning a
// balanced contiguous slice of ~22 rows. Streaming triple-dot with register
// carry (each row read once), zero barriers in the hot loop, inline margins,
// last-block-done deterministic global reduction.
// ---------------------------------------------------------------------------
__global__ __launch_bounds__(THREADS, 5)
void rank_fused_kernel(const float4* __restrict__ zi,
                       const float4* __restrict__ zt,
                       const int*    __restrict__ labels,
                       float*        __restrict__ out) {
    __shared__ float red[MAX_ROWS + 1][NWARPS][3];
    __shared__ float wsum[NWARPS];
    __shared__ int   is_last;

    const int t    = threadIdx.x;
    const int lane = t & 31;
    const int warp = t >> 5;
    const int RW   = D_DIM / 4;                       // 256 float4 per row

    // balanced contiguous partition of rows across GRID blocks
    const int start = (int)(((long)blockIdx.x       * B_ROWS) / GRID);
    const int end   = (int)(((long)(blockIdx.x + 1) * B_ROWS) / GRID);
    const int nrows = end - start;                    // 22 or 23

    // prime the carry with the first row of this slice
    float4 ci = zi[(long)start * RW + t];
    float4 ct = zt[(long)start * RW + t];

    // ---- streaming phase: no barriers ----
    #pragma unroll 4
    for (int k = 0; k < nrows; k++) {
        const int nr = (start + k + 1) & (B_ROWS - 1);

        float4 ni = zi[(long)nr * RW + t];
        float4 nt = zt[(long)nr * RW + t];

        float p = ci.x * ct.x + ci.y * ct.y + ci.z * ct.z + ci.w * ct.w;  // paired
        float a = ni.x * ct.x + ni.y * ct.y + ni.z * ct.z + ni.w * ct.w;  // imp_img
        float b = nt.x * ci.x + nt.y * ci.y + nt.z * ci.z + nt.w * ci.w;  // imp_txt

        #pragma unroll
        for (int o = 16; o > 0; o >>= 1) {
            p += __shfl_down_sync(0xffffffffu, p, o);
            a += __shfl_down_sync(0xffffffffu, a, o);
            b += __shfl_down_sync(0xffffffffu, b, o);
        }
        if (lane == 0) {
            red[k][warp][0] = p;
            red[k][warp][1] = a;
            red[k][warp][2] = b;
        }
        ci = ni;           // carry: next becomes current
        ct = nt;
    }

    __syncthreads();       // the ONLY barrier before the epilogue

    // ---- epilogue: threads 0..nrows-1 each finalize one row ----
    float acc = 0.0f;
    if (t < nrows) {
        const int r = start + t;
        const int j = (r + 1) & (B_ROWS - 1);

        // inline margin from labels (binary i32)
        const int* li = labels + (long)r * C_LAB;
        const int* lj = labels + (long)j * C_LAB;
        int n = 0, d = 0;
        bool eq = true;
        #pragma unroll
        for (int c = 0; c < C_LAB; c++) {
            int a = li[c], b = lj[c];
            eq = eq && (a == b);
            n += (a | b);
            d += (a ^ b);
        }
        float m;
        if (eq)         m = 0.0f;
        else if (n > 0) m = fmaxf(0.5f, (float)d / fmaxf((float)n, 1.0f));
        else            m = 0.5f;

        float P = 0.0f, A = 0.0f, Bv = 0.0f;
        #pragma unroll
        for (int w = 0; w < NWARPS; w++) {
            P  += red[t][w][0];
            A  += red[t][w][1];
            Bv += red[t][w][2];
        }
        acc = fmaxf(A - P + m, 0.0f) + fmaxf(Bv - P + m, 0.0f);
    }

    // nrows <= 23 < 32 -> all row-accs live in warp 0
    if (warp == 0) {
        #pragma unroll
        for (int o = 16; o > 0; o >>= 1)
            acc += __shfl_down_sync(0xffffffffu, acc, o);
        if (lane == 0) {
            g_partials[blockIdx.x] = acc;
            __threadfence();
            unsigned old = atomicAdd(&g_count, 1u);
            is_last = (old == GRID - 1) ? 1 : 0;
        }
    }
    __syncthreads();

    // ---- last block reduces all partials (fixed order -> deterministic) ----
    if (is_last) {
        float v = 0.0f;
        for (int i = t; i < GRID; i += THREADS)
            v += ((volatile float*)g_partials)[i];
        #pragma unroll
        for (int o = 16; o > 0; o >>= 1)
            v += __shfl_down_sync(0xffffffffu, v, o);
        if (lane == 0) wsum[warp] = v;
        __syncthreads();
        if (warp == 0) {
            float x = (lane < NWARPS) ? wsum[lane] : 0.0f;
            #pragma unroll
            for (int o = 4; o > 0; o >>= 1)
                x += __shfl_down_sync(0xffffffffu, x, o);
            if (t == 0) {
                out[0]  = x * (1.0f / (float)B_ROWS);
                g_count = 0;                 // reset for next graph replay
            }
        }
    }
}

// ---------------------------------------------------------------------------
extern "C" void kernel_launch(void* const* d_in, const int* in_sizes, int n_in,
                              void* d_out, int out_size) {
    const float* zi     = (const float*)d_in[0];   // z_image [16384,1024] f32
    const float* zt     = (const float*)d_in[1];   // z_text  [16384,1024] f32
    const int*   labels = (const int*)d_in[2];     // labels  [16384,14]   i32

    rank_fused_kernel<<<GRID, THREADS>>>((const float4*)zi, (const float4*)zt,
                                         labels, (float*)d_out);
}